// round 8
// baseline (speedup 1.0000x reference)
#include <cuda_runtime.h>
#include <math.h>

#define BATCH 8
#define SLEN  2048
#define DIM   512
#define MTOT  (BATCH*SLEN)

// ---------------- scratch ----------------
__device__ float g_qlin[MTOT*DIM];
__device__ float g_klin[MTOT*DIM];
__device__ float g_vlin[MTOT*DIM];
__device__ float g_q[MTOT*DIM];
__device__ float g_k[MTOT*DIM];
__device__ float g_v[MTOT*DIM];
__device__ float g_gate[MTOT*DIM];
__device__ float g_gdn[MTOT*DIM];
__device__ float g_fin[MTOT*DIM];
__device__ float g_alpha[MTOT];
__device__ float g_beta[MTOT];

// ---------------- packed f32x2 helpers ----------------
__device__ __forceinline__ unsigned long long fma2_(unsigned long long a,
                                                    unsigned long long b,
                                                    unsigned long long c) {
    unsigned long long d;
    asm("fma.rn.f32x2 %0, %1, %2, %3;" : "=l"(d) : "l"(a), "l"(b), "l"(c));
    return d;
}
__device__ __forceinline__ unsigned long long mul2_(unsigned long long a,
                                                    unsigned long long b) {
    unsigned long long d;
    asm("mul.rn.f32x2 %0, %1, %2;" : "=l"(d) : "l"(a), "l"(b));
    return d;
}
__device__ __forceinline__ unsigned long long pk2_(float lo, float hi) {
    unsigned long long r;
    asm("mov.b64 %0, {%1, %2};" : "=l"(r)
        : "r"(__float_as_uint(lo)), "r"(__float_as_uint(hi)));
    return r;
}
__device__ __forceinline__ void up2_(unsigned long long a, float& lo, float& hi) {
    unsigned int l, h;
    asm("mov.b64 {%0, %1}, %2;" : "=r"(l), "=r"(h) : "l"(a));
    lo = __uint_as_float(l); hi = __uint_as_float(h);
}
__device__ __forceinline__ float hadd2_(unsigned long long a) {
    float lo, hi; up2_(a, lo, hi); return lo + hi;
}
__device__ __forceinline__ float wredsum_(float v) {
    #pragma unroll
    for (int off = 16; off; off >>= 1) v += __shfl_xor_sync(0xffffffffu, v, off);
    return v;
}
__device__ __forceinline__ float silu_(float x) { return x / (1.0f + __expf(-x)); }
__device__ __forceinline__ void cpasync16_(unsigned int dst, const void* src) {
    asm volatile("cp.async.cg.shared.global [%0], [%1], 16;"
                 :: "r"(dst), "l"(src) : "memory");
}

// ---------------- GEMM: C[M,512] = A @ W^T + bias, optional SiLU ----------------
// 128x128 tile, BK=16, 256 threads, 8x8 per thread, double-buffered smem.
template<int ACT>
__global__ void __launch_bounds__(256, 2) sgemm_kernel(
    const float* __restrict__ A, const float* __restrict__ W,
    const float* __restrict__ bias, float* __restrict__ C)
{
    __shared__ float As[2][16][140];
    __shared__ float Bs[2][16][140];
    const int tid = threadIdx.x;
    const int m0 = blockIdx.x * 128;
    const int n0 = blockIdx.y * 128;
    const int tx = tid & 15;
    const int ty = tid >> 4;
    const int lrow = tid >> 1;
    const int lcol = (tid & 1) * 8;

    const float* Aptr = A + (size_t)(m0 + lrow) * DIM + lcol;
    const float* Wptr = W + (size_t)(n0 + lrow) * DIM + lcol;

    float4 a0 = *(const float4*)(Aptr + 0);
    float4 a1 = *(const float4*)(Aptr + 4);
    float4 w0 = *(const float4*)(Wptr + 0);
    float4 w1 = *(const float4*)(Wptr + 4);

    unsigned long long acc[8][4];
    #pragma unroll
    for (int i = 0; i < 8; i++)
        #pragma unroll
        for (int j = 0; j < 4; j++) acc[i][j] = 0ULL;

    int buf = 0;
    #pragma unroll 1
    for (int kb = 0; kb < DIM / 16; ++kb) {
        As[buf][lcol+0][lrow] = a0.x; As[buf][lcol+1][lrow] = a0.y;
        As[buf][lcol+2][lrow] = a0.z; As[buf][lcol+3][lrow] = a0.w;
        As[buf][lcol+4][lrow] = a1.x; As[buf][lcol+5][lrow] = a1.y;
        As[buf][lcol+6][lrow] = a1.z; As[buf][lcol+7][lrow] = a1.w;
        Bs[buf][lcol+0][lrow] = w0.x; Bs[buf][lcol+1][lrow] = w0.y;
        Bs[buf][lcol+2][lrow] = w0.z; Bs[buf][lcol+3][lrow] = w0.w;
        Bs[buf][lcol+4][lrow] = w1.x; Bs[buf][lcol+5][lrow] = w1.y;
        Bs[buf][lcol+6][lrow] = w1.z; Bs[buf][lcol+7][lrow] = w1.w;
        __syncthreads();

        if (kb + 1 < DIM / 16) {
            int k0 = (kb + 1) * 16;
            a0 = *(const float4*)(Aptr + k0 + 0);
            a1 = *(const float4*)(Aptr + k0 + 4);
            w0 = *(const float4*)(Wptr + k0 + 0);
            w1 = *(const float4*)(Wptr + k0 + 4);
        }

        const float (*as)[140] = As[buf];
        const float (*bs)[140] = Bs[buf];
        #pragma unroll
        for (int kk = 0; kk < 16; ++kk) {
            float4 af0 = *(const float4*)&as[kk][ty * 8];
            float4 af1 = *(const float4*)&as[kk][ty * 8 + 4];
            float4 bf0 = *(const float4*)&bs[kk][tx * 8];
            float4 bf1 = *(const float4*)&bs[kk][tx * 8 + 4];
            unsigned long long bb[4] = {
                pk2_(bf0.x, bf0.y), pk2_(bf0.z, bf0.w),
                pk2_(bf1.x, bf1.y), pk2_(bf1.z, bf1.w)
            };
            float av[8] = {af0.x, af0.y, af0.z, af0.w, af1.x, af1.y, af1.z, af1.w};
            #pragma unroll
            for (int i = 0; i < 8; i++) {
                unsigned long long am = pk2_(av[i], av[i]);
                #pragma unroll
                for (int j = 0; j < 4; j++)
                    acc[i][j] = fma2_(am, bb[j], acc[i][j]);
            }
        }
        buf ^= 1;
    }

    float4 bs0 = *(const float4*)(bias + n0 + tx * 8);
    float4 bs1 = *(const float4*)(bias + n0 + tx * 8 + 4);
    #pragma unroll
    for (int i = 0; i < 8; i++) {
        float c[8];
        up2_(acc[i][0], c[0], c[1]);
        up2_(acc[i][1], c[2], c[3]);
        up2_(acc[i][2], c[4], c[5]);
        up2_(acc[i][3], c[6], c[7]);
        c[0] += bs0.x; c[1] += bs0.y; c[2] += bs0.z; c[3] += bs0.w;
        c[4] += bs1.x; c[5] += bs1.y; c[6] += bs1.z; c[7] += bs1.w;
        if (ACT == 1) {
            #pragma unroll
            for (int j = 0; j < 8; j++) c[j] = silu_(c[j]);
        }
        float* cp = C + (size_t)(m0 + ty * 8 + i) * DIM + n0 + tx * 8;
        *(float4*)(cp)     = make_float4(c[0], c[1], c[2], c[3]);
        *(float4*)(cp + 4) = make_float4(c[4], c[5], c[6], c[7]);
    }
}

// ---------------- alpha/beta GEMV + sigmoid ----------------
__global__ void __launch_bounds__(256) ab_kernel(
    const float* __restrict__ x,
    const float* __restrict__ Wa, const float* __restrict__ ba,
    const float* __restrict__ Wb, const float* __restrict__ bb,
    float* __restrict__ alpha, float* __restrict__ beta)
{
    const int warp = threadIdx.x >> 5, lane = threadIdx.x & 31;
    const int m = blockIdx.x * 8 + warp;
    const float* xr = x + (size_t)m * DIM;
    float sa = 0.f, sb = 0.f;
    #pragma unroll
    for (int i = 0; i < 4; i++) {
        float4 xv = *(const float4*)(xr + i * 128 + (lane << 2));
        float4 wa = *(const float4*)(Wa + i * 128 + (lane << 2));
        float4 wb = *(const float4*)(Wb + i * 128 + (lane << 2));
        sa += xv.x*wa.x + xv.y*wa.y + xv.z*wa.z + xv.w*wa.w;
        sb += xv.x*wb.x + xv.y*wb.y + xv.z*wb.z + xv.w*wb.w;
    }
    sa = wredsum_(sa);
    sb = wredsum_(sb);
    if (lane == 0) {
        alpha[m] = 1.0f / (1.0f + __expf(-(sa + ba[0])));
        beta[m]  = 1.0f / (1.0f + __expf(-(sb + bb[0])));
    }
}

// ---------------- depthwise causal conv(4) + SiLU (+ optional L2 norm) ----------------
__global__ void __launch_bounds__(128) conv_silu_kernel(
    const float* __restrict__ lin, const float* __restrict__ cw,
    const float* __restrict__ cb, float* __restrict__ outp, int do_l2)
{
    __shared__ float red[4];
    const int m = blockIdx.x;
    const int s = m & (SLEN - 1);
    const int c = threadIdx.x << 2;
    const int lane = threadIdx.x & 31;
    const int warp = threadIdx.x >> 5;

    float w[4][4];
    #pragma unroll
    for (int ch = 0; ch < 4; ++ch) {
        float4 wv = *(const float4*)(cw + (size_t)(c + ch) * 4);
        w[ch][0] = wv.x; w[ch][1] = wv.y; w[ch][2] = wv.z; w[ch][3] = wv.w;
    }
    float4 bv = *(const float4*)(cb + c);
    float y0 = bv.x, y1 = bv.y, y2 = bv.z, y3 = bv.w;
    #pragma unroll
    for (int tau = 0; tau < 4; ++tau) {
        int sp = s - 3 + tau;
        if (sp >= 0) {
            float4 xv = *(const float4*)(lin + (size_t)(m - 3 + tau) * DIM + c);
            y0 += w[0][tau] * xv.x;
            y1 += w[1][tau] * xv.y;
            y2 += w[2][tau] * xv.z;
            y3 += w[3][tau] * xv.w;
        }
    }
    y0 = silu_(y0); y1 = silu_(y1); y2 = silu_(y2); y3 = silu_(y3);
    float sc = 1.0f;
    if (do_l2) {
        float ss = wredsum_(y0*y0 + y1*y1 + y2*y2 + y3*y3);
        if (lane == 0) red[warp] = ss;
        __syncthreads();
        float tot = red[0] + red[1] + red[2] + red[3];
        sc = 1.0f / fmaxf(sqrtf(tot), 1e-12f);
    }
    *(float4*)(outp + (size_t)m * DIM + c) = make_float4(y0*sc, y1*sc, y2*sc, y3*sc);
}

// ---------------- gated delta-rule scan ----------------
// 128 CTAs x 256 threads. Warp = 4 state rows; lane owns cols
// j = m*128 + lane*4 + {0..3}. Z = S/A, rescaled every 16 steps.
// k/q staged once per CTA per step in smem via 3-buffer cp.async pipeline
// (wait_group 1 => two steps of latency slack). One barrier per step.
// Merged reduction phase: 9 dots (zk0-3, zq0-3, kq) per step.
__global__ void __launch_bounds__(256, 1) scan_kernel(
    const float* __restrict__ qn, const float* __restrict__ kn,
    const float* __restrict__ vn, const float* __restrict__ alpha,
    const float* __restrict__ beta, float* __restrict__ outp)
{
    const int warp = threadIdx.x >> 5;
    const int lane = threadIdx.x & 31;
    const int cta  = blockIdx.x;
    const int b    = cta >> 4;
    const int i0   = ((cta & 15) << 5) + (warp << 2);

    const float* kp = kn + (size_t)b * SLEN * DIM;
    const float* qp = qn + (size_t)b * SLEN * DIM;
    const float* vp = vn + (size_t)b * SLEN * DIM + i0;
    const float* ap = alpha + (size_t)b * SLEN;
    const float* bp = beta  + (size_t)b * SLEN;
    float* op = outp + (size_t)b * SLEN * DIM + i0;

    // output-lane bookkeeping (validated in R6): 4-lane group g = lane>>2;
    // odd groups hold zq. g=1->row0, g=3->row2, g=5->row1, g=7->row3.
    const int g = lane >> 2;
    const bool isout = ((lane & 3) == 0) && (g & 1);
    const int h = g >> 1;
    const int orow = ((h & 1) << 1) | (h >> 1);

    // smem: 3 buffers x (k:512 | q:512 floats) = 12 KB
    __shared__ __align__(16) float sbuf[3][1024];
    unsigned int sbase = (unsigned int)__cvta_generic_to_shared(sbuf);
    const int half = threadIdx.x >> 7;          // 0: copies k, 1: copies q
    const int idx  = threadIdx.x & 127;
    const float* gsrc = (half ? qp : kp) + idx * 4;
    const unsigned int doff = half * 2048 + idx * 16;

    // prologue: t=0 -> buf0, t=1 -> buf1
    cpasync16_(sbase + doff, gsrc);
    asm volatile("cp.async.commit_group;" ::: "memory");
    cpasync16_(sbase + 4096 + doff, gsrc + DIM);
    asm volatile("cp.async.commit_group;" ::: "memory");

    unsigned long long z[4][8];
    #pragma unroll
    for (int r = 0; r < 4; r++)
        #pragma unroll
        for (int e = 0; e < 8; e++) z[r][e] = 0ULL;

    float A = 1.0f;
    const unsigned FULL = 0xffffffffu;
    int cur = 0, nxt = 2;

    #pragma unroll 1
    for (int t = 0; t < SLEN; ++t) {
        // copy(t) complete (<=1 pending: copy(t+1)); sync makes it CTA-visible
        // and guarantees all warps finished reading buf[nxt] (= step t-1's buf)
        asm volatile("cp.async.wait_group 1;" ::: "memory");
        __syncthreads();
        if (t + 2 < SLEN) {
            cpasync16_(sbase + nxt * 4096 + doff, gsrc + (size_t)(t + 2) * DIM);
        }
        asm volatile("cp.async.commit_group;" ::: "memory");

        // read k/q for step t from smem (conflict-free LDS.128)
        unsigned long long kc[8], qc[8];
        {
            const float4* kf = (const float4*)&sbuf[cur][0];
            const float4* qf = (const float4*)&sbuf[cur][512];
            #pragma unroll
            for (int m = 0; m < 4; m++) {
                float4 kv = kf[m * 32 + lane];
                kc[2*m]   = pk2_(kv.x, kv.y);
                kc[2*m+1] = pk2_(kv.z, kv.w);
                float4 qv = qf[m * 32 + lane];
                qc[2*m]   = pk2_(qv.x, qv.y);
                qc[2*m+1] = pk2_(qv.z, qv.w);
            }
        }
        float4 v4 = *(const float4*)(vp + (size_t)t * DIM);
        float at = __ldg(ap + t);
        float bt = __ldg(bp + t);

        // 9 simultaneous dots on Z_old
        unsigned long long zka[4] = {0,0,0,0};
        unsigned long long zqa[4] = {0,0,0,0};
        unsigned long long kqa = 0;
        #pragma unroll
        for (int e = 0; e < 8; e++) {
            zka[0] = fma2_(z[0][e], kc[e], zka[0]);
            zka[1] = fma2_(z[1][e], kc[e], zka[1]);
            zka[2] = fma2_(z[2][e], kc[e], zka[2]);
            zka[3] = fma2_(z[3][e], kc[e], zka[3]);
            zqa[0] = fma2_(z[0][e], qc[e], zqa[0]);
            zqa[1] = fma2_(z[1][e], qc[e], zqa[1]);
            zqa[2] = fma2_(z[2][e], qc[e], zqa[2]);
            zqa[3] = fma2_(z[3][e], qc[e], zqa[3]);
            kqa    = fma2_(kc[e],   qc[e], kqa);
        }
        float a0 = hadd2_(zka[0]), a1 = hadd2_(zka[1]);
        float a2 = hadd2_(zka[2]), a3 = hadd2_(zka[3]);
        float c0 = hadd2_(zqa[0]), c1 = hadd2_(zqa[1]);
        float c2 = hadd2_(zqa[2]), c3 = hadd2_(zqa[3]);
        float kq = hadd2_(kqa);

        // packed 8-value butterfly (16 shfls)
        float p0, p1, p2, p3;
        {
            float x0 = a0 + __shfl_xor_sync(FULL, a0, 16);
            float x1 = a1 + __shfl_xor_sync(FULL, a1, 16);
            float x2 = a2 + __shfl_xor_sync(FULL, a2, 16);
            float x3 = a3 + __shfl_xor_sync(FULL, a3, 16);
            float y0 = c0 + __shfl_xor_sync(FULL, c0, 16);
            float y1 = c1 + __shfl_xor_sync(FULL, c1, 16);
            float y2 = c2 + __shfl_xor_sync(FULL, c2, 16);
            float y3 = c3 + __shfl_xor_sync(FULL, c3, 16);
            bool hi = (lane & 16) != 0;
            p0 = hi ? x1 : x0;
            p1 = hi ? x3 : x2;
            p2 = hi ? y1 : y0;
            p3 = hi ? y3 : y2;
        }
        float r0, r1;
        {
            float x0 = p0 + __shfl_xor_sync(FULL, p0, 8);
            float x1 = p1 + __shfl_xor_sync(FULL, p1, 8);
            float y0 = p2 + __shfl_xor_sync(FULL, p2, 8);
            float y1 = p3 + __shfl_xor_sync(FULL, p3, 8);
            bool hi = (lane & 8) != 0;
            r0 = hi ? x1 : x0;
            r1 = hi ? y1 : y0;
        }
        float s;
        {
            float x0 = r0 + __shfl_xor_sync(FULL, r0, 4);
            float y0 = r1 + __shfl_xor_sync(FULL, r1, 4);
            s = (lane & 4) ? y0 : x0;
        }
        s += __shfl_xor_sync(FULL, s, 2);
        s += __shfl_xor_sync(FULL, s, 1);

        kq = wredsum_(kq);

        float zk0 = __shfl_sync(FULL, s, 0);
        float zk2 = __shfl_sync(FULL, s, 8);
        float zk1 = __shfl_sync(FULL, s, 16);
        float zk3 = __shfl_sync(FULL, s, 24);

        float An  = A * at;
        float rAn = 1.0f / An;
        float ab  = at * bt;
        float w0 = (bt * v4.x - ab * (A * zk0)) * rAn;
        float w1 = (bt * v4.y - ab * (A * zk1)) * rAn;
        float w2 = (bt * v4.z - ab * (A * zk2)) * rAn;
        float w3 = (bt * v4.w - ab * (A * zk3)) * rAn;

        unsigned long long W0 = pk2_(w0, w0), W1 = pk2_(w1, w1);
        unsigned long long W2 = pk2_(w2, w2), W3 = pk2_(w3, w3);
        #pragma unroll
        for (int e = 0; e < 8; e++) {
            z[0][e] = fma2_(W0, kc[e], z[0][e]);
            z[1][e] = fma2_(W1, kc[e], z[1][e]);
            z[2][e] = fma2_(W2, kc[e], z[2][e]);
            z[3][e] = fma2_(W3, kc[e], z[3][e]);
        }

        if (isout) {
            float wr = (h == 0) ? w0 : (h == 1) ? w2 : (h == 2) ? w1 : w3;
            op[(size_t)t * DIM + orow] = An * (s + wr * kq);
        }

        A = An;
        if ((t & 15) == 15) {
            unsigned long long A2 = pk2_(A, A);
            #pragma unroll
            for (int r = 0; r < 4; r++)
                #pragma unroll
                for (int e = 0; e < 8; e++) z[r][e] = mul2_(z[r][e], A2);
            A = 1.0f;
        }

        cur = (cur == 2) ? 0 : cur + 1;
        nxt = (nxt == 2) ? 0 : nxt + 1;
    }
}

// ---------------- zero-centered RMSNorm * gate ----------------
__global__ void __launch_bounds__(128) norm_gate_kernel(
    const float* __restrict__ gdn, const float* __restrict__ norm_w,
    const float* __restrict__ gate, float* __restrict__ fin)
{
    __shared__ float rs[4], rq[4];
    const int m = blockIdx.x;
    const int c = threadIdx.x << 2;
    const int lane = threadIdx.x & 31;
    const int warp = threadIdx.x >> 5;

    float4 xv = *(const float4*)(gdn + (size_t)m * DIM + c);
    float s = wredsum_(xv.x + xv.y + xv.z + xv.w);
    float q = wredsum_(xv.x*xv.x + xv.y*xv.y + xv.z*xv.z + xv.w*xv.w);
    if (lane == 0) { rs[warp] = s; rq[warp] = q; }
    __syncthreads();
    float sum = rs[0] + rs[1] + rs[2] + rs[3];
    float sq  = rq[0] + rq[1] + rq[2] + rq[3];
    float mean = sum * (1.0f / DIM);
    float var  = sq * (1.0f / DIM) - mean * mean;
    float inv  = rsqrtf(var + 1e-5f);

    float4 wv = *(const float4*)(norm_w + c);
    float4 gv = *(const float4*)(gate + (size_t)m * DIM + c);
    float4 r;
    r.x = (xv.x - mean) * inv * wv.x * gv.x;
    r.y = (xv.y - mean) * inv * wv.y * gv.y;
    r.z = (xv.z - mean) * inv * wv.z * gv.z;
    r.w = (xv.w - mean) * inv * wv.w * gv.w;
    *(float4*)(fin + (size_t)m * DIM + c) = r;
}

// ---------------- launch ----------------
extern "C" void kernel_launch(void* const* d_in, const int* in_sizes, int n_in,
                              void* d_out, int out_size) {
    const float* x    = (const float*)d_in[0];
    const float* Wq   = (const float*)d_in[1];
    const float* bq   = (const float*)d_in[2];
    const float* Wk   = (const float*)d_in[3];
    const float* bk   = (const float*)d_in[4];
    const float* Wv   = (const float*)d_in[5];
    const float* bv   = (const float*)d_in[6];
    const float* Wa   = (const float*)d_in[7];
    const float* ba   = (const float*)d_in[8];
    const float* Wb   = (const float*)d_in[9];
    const float* bb   = (const float*)d_in[10];
    const float* cwq  = (const float*)d_in[11];
    const float* cbq  = (const float*)d_in[12];
    const float* cwk  = (const float*)d_in[13];
    const float* cbk  = (const float*)d_in[14];
    const float* cwv  = (const float*)d_in[15];
    const float* cbv  = (const float*)d_in[16];
    const float* norm_w = (const float*)d_in[17];
    const float* Wg   = (const float*)d_in[18];
    const float* bg   = (const float*)d_in[19];
    const float* Wo   = (const float*)d_in[20];
    const float* bo   = (const float*)d_in[21];
    float* out = (float*)d_out;

    float *qlin, *klin, *vlin, *qn, *kn, *vn, *gate, *gdn, *fin, *al, *be;
    cudaGetSymbolAddress((void**)&qlin, g_qlin);
    cudaGetSymbolAddress((void**)&klin, g_klin);
    cudaGetSymbolAddress((void**)&vlin, g_vlin);
    cudaGetSymbolAddress((void**)&qn,   g_q);
    cudaGetSymbolAddress((void**)&kn,   g_k);
    cudaGetSymbolAddress((void**)&vn,   g_v);
    cudaGetSymbolAddress((void**)&gate, g_gate);
    cudaGetSymbolAddress((void**)&gdn,  g_gdn);
    cudaGetSymbolAddress((void**)&fin,  g_fin);
    cudaGetSymbolAddress((void**)&al,   g_alpha);
    cudaGetSymbolAddress((void**)&be,   g_beta);

    dim3 gg(MTOT / 128, DIM / 128);
    sgemm_kernel<0><<<gg, 256>>>(x, Wq, bq, qlin);
    sgemm_kernel<0><<<gg, 256>>>(x, Wk, bk, klin);
    sgemm_kernel<0><<<gg, 256>>>(x, Wv, bv, vlin);
    sgemm_kernel<1><<<gg, 256>>>(x, Wg, bg, gate);
    ab_kernel<<<MTOT / 8, 256>>>(x, Wa, ba, Wb, bb, al, be);

    conv_silu_kernel<<<MTOT, 128>>>(qlin, cwq, cbq, qn, 1);
    conv_silu_kernel<<<MTOT, 128>>>(klin, cwk, cbk, kn, 1);
    conv_silu_kernel<<<MTOT, 128>>>(vlin, cwv, cbv, vn, 0);

    scan_kernel<<<128, 256>>>(qn, kn, vn, al, be, gdn);

    norm_gate_kernel<<<MTOT, 128>>>(gdn, norm_w, gate, fin);
    sgemm_kernel<0><<<gg, 256>>>(fin, Wo, bo, out);
}

// round 9
// speedup vs baseline: 1.0447x; 1.0447x over previous
#include <cuda_runtime.h>
#include <math.h>

#define BATCH 8
#define SLEN  2048
#define DIM   512
#define MTOT  (BATCH*SLEN)

// ---------------- scratch ----------------
__device__ float g_qlin[MTOT*DIM];
__device__ float g_klin[MTOT*DIM];
__device__ float g_vlin[MTOT*DIM];
__device__ float g_q[MTOT*DIM];
__device__ float g_k[MTOT*DIM];
__device__ float g_v[MTOT*DIM];
__device__ float g_gate[MTOT*DIM];
__device__ float g_gdn[MTOT*DIM];
__device__ float g_fin[MTOT*DIM];
__device__ float g_alpha[MTOT];
__device__ float g_beta[MTOT];

// ---------------- packed f32x2 helpers ----------------
__device__ __forceinline__ unsigned long long fma2_(unsigned long long a,
                                                    unsigned long long b,
                                                    unsigned long long c) {
    unsigned long long d;
    asm("fma.rn.f32x2 %0, %1, %2, %3;" : "=l"(d) : "l"(a), "l"(b), "l"(c));
    return d;
}
__device__ __forceinline__ unsigned long long mul2_(unsigned long long a,
                                                    unsigned long long b) {
    unsigned long long d;
    asm("mul.rn.f32x2 %0, %1, %2;" : "=l"(d) : "l"(a), "l"(b));
    return d;
}
__device__ __forceinline__ unsigned long long pk2_(float lo, float hi) {
    unsigned long long r;
    asm("mov.b64 %0, {%1, %2};" : "=l"(r)
        : "r"(__float_as_uint(lo)), "r"(__float_as_uint(hi)));
    return r;
}
__device__ __forceinline__ void up2_(unsigned long long a, float& lo, float& hi) {
    unsigned int l, h;
    asm("mov.b64 {%0, %1}, %2;" : "=r"(l), "=r"(h) : "l"(a));
    lo = __uint_as_float(l); hi = __uint_as_float(h);
}
__device__ __forceinline__ float hadd2_(unsigned long long a) {
    float lo, hi; up2_(a, lo, hi); return lo + hi;
}
__device__ __forceinline__ float wredsum_(float v) {
    #pragma unroll
    for (int off = 16; off; off >>= 1) v += __shfl_xor_sync(0xffffffffu, v, off);
    return v;
}
__device__ __forceinline__ float silu_(float x) { return x / (1.0f + __expf(-x)); }
__device__ __forceinline__ void cpasync16_(unsigned int dst, const void* src) {
    asm volatile("cp.async.cg.shared.global [%0], [%1], 16;"
                 :: "r"(dst), "l"(src) : "memory");
}

// ---------------- GEMM: C[M,512] = A @ W^T + bias, optional SiLU ----------------
// 128x128 tile, BK=16, 256 threads, 8x8 per thread, double-buffered smem.
template<int ACT>
__global__ void __launch_bounds__(256, 2) sgemm_kernel(
    const float* __restrict__ A, const float* __restrict__ W,
    const float* __restrict__ bias, float* __restrict__ C)
{
    __shared__ float As[2][16][140];
    __shared__ float Bs[2][16][140];
    const int tid = threadIdx.x;
    const int m0 = blockIdx.x * 128;
    const int n0 = blockIdx.y * 128;
    const int tx = tid & 15;
    const int ty = tid >> 4;
    const int lrow = tid >> 1;
    const int lcol = (tid & 1) * 8;

    const float* Aptr = A + (size_t)(m0 + lrow) * DIM + lcol;
    const float* Wptr = W + (size_t)(n0 + lrow) * DIM + lcol;

    float4 a0 = *(const float4*)(Aptr + 0);
    float4 a1 = *(const float4*)(Aptr + 4);
    float4 w0 = *(const float4*)(Wptr + 0);
    float4 w1 = *(const float4*)(Wptr + 4);

    unsigned long long acc[8][4];
    #pragma unroll
    for (int i = 0; i < 8; i++)
        #pragma unroll
        for (int j = 0; j < 4; j++) acc[i][j] = 0ULL;

    int buf = 0;
    #pragma unroll 1
    for (int kb = 0; kb < DIM / 16; ++kb) {
        As[buf][lcol+0][lrow] = a0.x; As[buf][lcol+1][lrow] = a0.y;
        As[buf][lcol+2][lrow] = a0.z; As[buf][lcol+3][lrow] = a0.w;
        As[buf][lcol+4][lrow] = a1.x; As[buf][lcol+5][lrow] = a1.y;
        As[buf][lcol+6][lrow] = a1.z; As[buf][lcol+7][lrow] = a1.w;
        Bs[buf][lcol+0][lrow] = w0.x; Bs[buf][lcol+1][lrow] = w0.y;
        Bs[buf][lcol+2][lrow] = w0.z; Bs[buf][lcol+3][lrow] = w0.w;
        Bs[buf][lcol+4][lrow] = w1.x; Bs[buf][lcol+5][lrow] = w1.y;
        Bs[buf][lcol+6][lrow] = w1.z; Bs[buf][lcol+7][lrow] = w1.w;
        __syncthreads();

        if (kb + 1 < DIM / 16) {
            int k0 = (kb + 1) * 16;
            a0 = *(const float4*)(Aptr + k0 + 0);
            a1 = *(const float4*)(Aptr + k0 + 4);
            w0 = *(const float4*)(Wptr + k0 + 0);
            w1 = *(const float4*)(Wptr + k0 + 4);
        }

        const float (*as)[140] = As[buf];
        const float (*bs)[140] = Bs[buf];
        #pragma unroll
        for (int kk = 0; kk < 16; ++kk) {
            float4 af0 = *(const float4*)&as[kk][ty * 8];
            float4 af1 = *(const float4*)&as[kk][ty * 8 + 4];
            float4 bf0 = *(const float4*)&bs[kk][tx * 8];
            float4 bf1 = *(const float4*)&bs[kk][tx * 8 + 4];
            unsigned long long bb[4] = {
                pk2_(bf0.x, bf0.y), pk2_(bf0.z, bf0.w),
                pk2_(bf1.x, bf1.y), pk2_(bf1.z, bf1.w)
            };
            float av[8] = {af0.x, af0.y, af0.z, af0.w, af1.x, af1.y, af1.z, af1.w};
            #pragma unroll
            for (int i = 0; i < 8; i++) {
                unsigned long long am = pk2_(av[i], av[i]);
                #pragma unroll
                for (int j = 0; j < 4; j++)
                    acc[i][j] = fma2_(am, bb[j], acc[i][j]);
            }
        }
        buf ^= 1;
    }

    float4 bs0 = *(const float4*)(bias + n0 + tx * 8);
    float4 bs1 = *(const float4*)(bias + n0 + tx * 8 + 4);
    #pragma unroll
    for (int i = 0; i < 8; i++) {
        float c[8];
        up2_(acc[i][0], c[0], c[1]);
        up2_(acc[i][1], c[2], c[3]);
        up2_(acc[i][2], c[4], c[5]);
        up2_(acc[i][3], c[6], c[7]);
        c[0] += bs0.x; c[1] += bs0.y; c[2] += bs0.z; c[3] += bs0.w;
        c[4] += bs1.x; c[5] += bs1.y; c[6] += bs1.z; c[7] += bs1.w;
        if (ACT == 1) {
            #pragma unroll
            for (int j = 0; j < 8; j++) c[j] = silu_(c[j]);
        }
        float* cp = C + (size_t)(m0 + ty * 8 + i) * DIM + n0 + tx * 8;
        *(float4*)(cp)     = make_float4(c[0], c[1], c[2], c[3]);
        *(float4*)(cp + 4) = make_float4(c[4], c[5], c[6], c[7]);
    }
}

// ---------------- alpha/beta GEMV + sigmoid ----------------
__global__ void __launch_bounds__(256) ab_kernel(
    const float* __restrict__ x,
    const float* __restrict__ Wa, const float* __restrict__ ba,
    const float* __restrict__ Wb, const float* __restrict__ bb,
    float* __restrict__ alpha, float* __restrict__ beta)
{
    const int warp = threadIdx.x >> 5, lane = threadIdx.x & 31;
    const int m = blockIdx.x * 8 + warp;
    const float* xr = x + (size_t)m * DIM;
    float sa = 0.f, sb = 0.f;
    #pragma unroll
    for (int i = 0; i < 4; i++) {
        float4 xv = *(const float4*)(xr + i * 128 + (lane << 2));
        float4 wa = *(const float4*)(Wa + i * 128 + (lane << 2));
        float4 wb = *(const float4*)(Wb + i * 128 + (lane << 2));
        sa += xv.x*wa.x + xv.y*wa.y + xv.z*wa.z + xv.w*wa.w;
        sb += xv.x*wb.x + xv.y*wb.y + xv.z*wb.z + xv.w*wb.w;
    }
    sa = wredsum_(sa);
    sb = wredsum_(sb);
    if (lane == 0) {
        alpha[m] = 1.0f / (1.0f + __expf(-(sa + ba[0])));
        beta[m]  = 1.0f / (1.0f + __expf(-(sb + bb[0])));
    }
}

// ---------------- depthwise causal conv(4) + SiLU (+ optional L2 norm) ----------------
__global__ void __launch_bounds__(128) conv_silu_kernel(
    const float* __restrict__ lin, const float* __restrict__ cw,
    const float* __restrict__ cb, float* __restrict__ outp, int do_l2)
{
    __shared__ float red[4];
    const int m = blockIdx.x;
    const int s = m & (SLEN - 1);
    const int c = threadIdx.x << 2;
    const int lane = threadIdx.x & 31;
    const int warp = threadIdx.x >> 5;

    float w[4][4];
    #pragma unroll
    for (int ch = 0; ch < 4; ++ch) {
        float4 wv = *(const float4*)(cw + (size_t)(c + ch) * 4);
        w[ch][0] = wv.x; w[ch][1] = wv.y; w[ch][2] = wv.z; w[ch][3] = wv.w;
    }
    float4 bv = *(const float4*)(cb + c);
    float y0 = bv.x, y1 = bv.y, y2 = bv.z, y3 = bv.w;
    #pragma unroll
    for (int tau = 0; tau < 4; ++tau) {
        int sp = s - 3 + tau;
        if (sp >= 0) {
            float4 xv = *(const float4*)(lin + (size_t)(m - 3 + tau) * DIM + c);
            y0 += w[0][tau] * xv.x;
            y1 += w[1][tau] * xv.y;
            y2 += w[2][tau] * xv.z;
            y3 += w[3][tau] * xv.w;
        }
    }
    y0 = silu_(y0); y1 = silu_(y1); y2 = silu_(y2); y3 = silu_(y3);
    float sc = 1.0f;
    if (do_l2) {
        float ss = wredsum_(y0*y0 + y1*y1 + y2*y2 + y3*y3);
        if (lane == 0) red[warp] = ss;
        __syncthreads();
        float tot = red[0] + red[1] + red[2] + red[3];
        sc = 1.0f / fmaxf(sqrtf(tot), 1e-12f);
    }
    *(float4*)(outp + (size_t)m * DIM + c) = make_float4(y0*sc, y1*sc, y2*sc, y3*sc);
}

// ---------------- gated delta-rule scan ----------------
// 256 CTAs x 128 threads (4 warps). Warp = 4 state rows; 16 rows/CTA.
// 2 independent CTAs/SM -> cross-CTA latency hiding (barriers don't couple).
// k/q staged once per CTA per step in smem via 3-buffer cp.async pipeline
// (wait_group 1 => two steps of slack). One barrier per step.
// Merged reduction phase: 9 dots (zk0-3, zq0-3, kq) per step.
__global__ void __launch_bounds__(128, 2) scan_kernel(
    const float* __restrict__ qn, const float* __restrict__ kn,
    const float* __restrict__ vn, const float* __restrict__ alpha,
    const float* __restrict__ beta, float* __restrict__ outp)
{
    const int warp = threadIdx.x >> 5;           // 0..3
    const int lane = threadIdx.x & 31;
    const int cta  = blockIdx.x;                 // 0..255
    const int b    = cta >> 5;                   // 32 CTAs per batch
    const int i0   = ((cta & 31) << 4) + (warp << 2);  // 16 rows/CTA, 4/warp

    const float* kp = kn + (size_t)b * SLEN * DIM;
    const float* qp = qn + (size_t)b * SLEN * DIM;
    const float* vp = vn + (size_t)b * SLEN * DIM + i0;
    const float* ap = alpha + (size_t)b * SLEN;
    const float* bp = beta  + (size_t)b * SLEN;
    float* op = outp + (size_t)b * SLEN * DIM + i0;

    // output-lane bookkeeping (validated R6/R8): group g = lane>>2; odd
    // groups hold zq. g=1->row0, g=3->row2, g=5->row1, g=7->row3.
    const int g = lane >> 2;
    const bool isout = ((lane & 3) == 0) && (g & 1);
    const int h = g >> 1;
    const int orow = ((h & 1) << 1) | (h >> 1);

    // smem: 3 buffers x (k:512 | q:512 floats) = 12 KB
    __shared__ __align__(16) float sbuf[3][1024];
    unsigned int sbase = (unsigned int)__cvta_generic_to_shared(sbuf);
    // 128 threads stage 4KB/step: threads 0-63 copy k (2 float4 each),
    // threads 64-127 copy q.
    const int half = threadIdx.x >> 6;           // 0: k, 1: q
    const int idx  = threadIdx.x & 63;           // float4 index 0..63
    const float* gsrc = (half ? qp : kp) + idx * 4;
    const unsigned int doff = half * 2048 + idx * 16;

    // prologue: t=0 -> buf0, t=1 -> buf1
    cpasync16_(sbase + doff,        gsrc);
    cpasync16_(sbase + doff + 1024, gsrc + 256);
    asm volatile("cp.async.commit_group;" ::: "memory");
    cpasync16_(sbase + 4096 + doff,        gsrc + DIM);
    cpasync16_(sbase + 4096 + doff + 1024, gsrc + DIM + 256);
    asm volatile("cp.async.commit_group;" ::: "memory");

    unsigned long long z[4][8];
    #pragma unroll
    for (int r = 0; r < 4; r++)
        #pragma unroll
        for (int e = 0; e < 8; e++) z[r][e] = 0ULL;

    float A = 1.0f;
    const unsigned FULL = 0xffffffffu;
    int cur = 0, nxt = 2;

    #pragma unroll 1
    for (int t = 0; t < SLEN; ++t) {
        // copy(t) complete (<=1 pending: copy(t+1)); barrier makes it
        // CTA-visible and covers reuse of buf[nxt] (read at step t-1).
        asm volatile("cp.async.wait_group 1;" ::: "memory");
        __syncthreads();
        if (t + 2 < SLEN) {
            const float* gs2 = gsrc + (size_t)(t + 2) * DIM;
            cpasync16_(sbase + nxt * 4096 + doff,        gs2);
            cpasync16_(sbase + nxt * 4096 + doff + 1024, gs2 + 256);
        }
        asm volatile("cp.async.commit_group;" ::: "memory");

        // read k/q for step t from smem (conflict-free LDS.128)
        unsigned long long kc[8], qc[8];
        {
            const float4* kf = (const float4*)&sbuf[cur][0];
            const float4* qf = (const float4*)&sbuf[cur][512];
            #pragma unroll
            for (int m = 0; m < 4; m++) {
                float4 kv = kf[m * 32 + lane];
                kc[2*m]   = pk2_(kv.x, kv.y);
                kc[2*m+1] = pk2_(kv.z, kv.w);
                float4 qv = qf[m * 32 + lane];
                qc[2*m]   = pk2_(qv.x, qv.y);
                qc[2*m+1] = pk2_(qv.z, qv.w);
            }
        }
        float4 v4 = *(const float4*)(vp + (size_t)t * DIM);
        float at = __ldg(ap + t);
        float bt = __ldg(bp + t);

        // 9 simultaneous dots on Z_old
        unsigned long long zka[4] = {0,0,0,0};
        unsigned long long zqa[4] = {0,0,0,0};
        unsigned long long kqa = 0;
        #pragma unroll
        for (int e = 0; e < 8; e++) {
            zka[0] = fma2_(z[0][e], kc[e], zka[0]);
            zka[1] = fma2_(z[1][e], kc[e], zka[1]);
            zka[2] = fma2_(z[2][e], kc[e], zka[2]);
            zka[3] = fma2_(z[3][e], kc[e], zka[3]);
            zqa[0] = fma2_(z[0][e], qc[e], zqa[0]);
            zqa[1] = fma2_(z[1][e], qc[e], zqa[1]);
            zqa[2] = fma2_(z[2][e], qc[e], zqa[2]);
            zqa[3] = fma2_(z[3][e], qc[e], zqa[3]);
            kqa    = fma2_(kc[e],   qc[e], kqa);
        }
        float a0 = hadd2_(zka[0]), a1 = hadd2_(zka[1]);
        float a2 = hadd2_(zka[2]), a3 = hadd2_(zka[3]);
        float c0 = hadd2_(zqa[0]), c1 = hadd2_(zqa[1]);
        float c2 = hadd2_(zqa[2]), c3 = hadd2_(zqa[3]);
        float kq = hadd2_(kqa);

        // packed 8-value butterfly (16 shfls)
        float p0, p1, p2, p3;
        {
            float x0 = a0 + __shfl_xor_sync(FULL, a0, 16);
            float x1 = a1 + __shfl_xor_sync(FULL, a1, 16);
            float x2 = a2 + __shfl_xor_sync(FULL, a2, 16);
            float x3 = a3 + __shfl_xor_sync(FULL, a3, 16);
            float y0 = c0 + __shfl_xor_sync(FULL, c0, 16);
            float y1 = c1 + __shfl_xor_sync(FULL, c1, 16);
            float y2 = c2 + __shfl_xor_sync(FULL, c2, 16);
            float y3 = c3 + __shfl_xor_sync(FULL, c3, 16);
            bool hi = (lane & 16) != 0;
            p0 = hi ? x1 : x0;
            p1 = hi ? x3 : x2;
            p2 = hi ? y1 : y0;
            p3 = hi ? y3 : y2;
        }
        float r0, r1;
        {
            float x0 = p0 + __shfl_xor_sync(FULL, p0, 8);
            float x1 = p1 + __shfl_xor_sync(FULL, p1, 8);
            float y0 = p2 + __shfl_xor_sync(FULL, p2, 8);
            float y1 = p3 + __shfl_xor_sync(FULL, p3, 8);
            bool hi = (lane & 8) != 0;
            r0 = hi ? x1 : x0;
            r1 = hi ? y1 : y0;
        }
        float s;
        {
            float x0 = r0 + __shfl_xor_sync(FULL, r0, 4);
            float y0 = r1 + __shfl_xor_sync(FULL, r1, 4);
            s = (lane & 4) ? y0 : x0;
        }
        s += __shfl_xor_sync(FULL, s, 2);
        s += __shfl_xor_sync(FULL, s, 1);

        kq = wredsum_(kq);

        float zk0 = __shfl_sync(FULL, s, 0);
        float zk2 = __shfl_sync(FULL, s, 8);
        float zk1 = __shfl_sync(FULL, s, 16);
        float zk3 = __shfl_sync(FULL, s, 24);

        float An  = A * at;
        float rAn = 1.0f / An;
        float ab  = at * bt;
        float w0 = (bt * v4.x - ab * (A * zk0)) * rAn;
        float w1 = (bt * v4.y - ab * (A * zk1)) * rAn;
        float w2 = (bt * v4.z - ab * (A * zk2)) * rAn;
        float w3 = (bt * v4.w - ab * (A * zk3)) * rAn;

        unsigned long long W0 = pk2_(w0, w0), W1 = pk2_(w1, w1);
        unsigned long long W2 = pk2_(w2, w2), W3 = pk2_(w3, w3);
        #pragma unroll
        for (int e = 0; e < 8; e++) {
            z[0][e] = fma2_(W0, kc[e], z[0][e]);
            z[1][e] = fma2_(W1, kc[e], z[1][e]);
            z[2][e] = fma2_(W2, kc[e], z[2][e]);
            z[3][e] = fma2_(W3, kc[e], z[3][e]);
        }

        if (isout) {
            float wr = (h == 0) ? w0 : (h == 1) ? w2 : (h == 2) ? w1 : w3;
            op[(size_t)t * DIM + orow] = An * (s + wr * kq);
        }

        A = An;
        if ((t & 15) == 15) {
            unsigned long long A2 = pk2_(A, A);
            #pragma unroll
            for (int r = 0; r < 4; r++)
                #pragma unroll
                for (int e = 0; e < 8; e++) z[r][e] = mul2_(z[r][e], A2);
            A = 1.0f;
        }

        cur = (cur == 2) ? 0 : cur + 1;
        nxt = (nxt == 2) ? 0 : nxt + 1;
    }
}

// ---------------- zero-centered RMSNorm * gate ----------------
__global__ void __launch_bounds__(128) norm_gate_kernel(
    const float* __restrict__ gdn, const float* __restrict__ norm_w,
    const float* __restrict__ gate, float* __restrict__ fin)
{
    __shared__ float rs[4], rq[4];
    const int m = blockIdx.x;
    const int c = threadIdx.x << 2;
    const int lane = threadIdx.x & 31;
    const int warp = threadIdx.x >> 5;

    float4 xv = *(const float4*)(gdn + (size_t)m * DIM + c);
    float s = wredsum_(xv.x + xv.y + xv.z + xv.w);
    float q = wredsum_(xv.x*xv.x + xv.y*xv.y + xv.z*xv.z + xv.w*xv.w);
    if (lane == 0) { rs[warp] = s; rq[warp] = q; }
    __syncthreads();
    float sum = rs[0] + rs[1] + rs[2] + rs[3];
    float sq  = rq[0] + rq[1] + rq[2] + rq[3];
    float mean = sum * (1.0f / DIM);
    float var  = sq * (1.0f / DIM) - mean * mean;
    float inv  = rsqrtf(var + 1e-5f);

    float4 wv = *(const float4*)(norm_w + c);
    float4 gv = *(const float4*)(gate + (size_t)m * DIM + c);
    float4 r;
    r.x = (xv.x - mean) * inv * wv.x * gv.x;
    r.y = (xv.y - mean) * inv * wv.y * gv.y;
    r.z = (xv.z - mean) * inv * wv.z * gv.z;
    r.w = (xv.w - mean) * inv * wv.w * gv.w;
    *(float4*)(fin + (size_t)m * DIM + c) = r;
}

// ---------------- launch ----------------
extern "C" void kernel_launch(void* const* d_in, const int* in_sizes, int n_in,
                              void* d_out, int out_size) {
    const float* x    = (const float*)d_in[0];
    const float* Wq   = (const float*)d_in[1];
    const float* bq   = (const float*)d_in[2];
    const float* Wk   = (const float*)d_in[3];
    const float* bk   = (const float*)d_in[4];
    const float* Wv   = (const float*)d_in[5];
    const float* bv   = (const float*)d_in[6];
    const float* Wa   = (const float*)d_in[7];
    const float* ba   = (const float*)d_in[8];
    const float* Wb   = (const float*)d_in[9];
    const float* bb   = (const float*)d_in[10];
    const float* cwq  = (const float*)d_in[11];
    const float* cbq  = (const float*)d_in[12];
    const float* cwk  = (const float*)d_in[13];
    const float* cbk  = (const float*)d_in[14];
    const float* cwv  = (const float*)d_in[15];
    const float* cbv  = (const float*)d_in[16];
    const float* norm_w = (const float*)d_in[17];
    const float* Wg   = (const float*)d_in[18];
    const float* bg   = (const float*)d_in[19];
    const float* Wo   = (const float*)d_in[20];
    const float* bo   = (const float*)d_in[21];
    float* out = (float*)d_out;

    float *qlin, *klin, *vlin, *qn, *kn, *vn, *gate, *gdn, *fin, *al, *be;
    cudaGetSymbolAddress((void**)&qlin, g_qlin);
    cudaGetSymbolAddress((void**)&klin, g_klin);
    cudaGetSymbolAddress((void**)&vlin, g_vlin);
    cudaGetSymbolAddress((void**)&qn,   g_q);
    cudaGetSymbolAddress((void**)&kn,   g_k);
    cudaGetSymbolAddress((void**)&vn,   g_v);
    cudaGetSymbolAddress((void**)&gate, g_gate);
    cudaGetSymbolAddress((void**)&gdn,  g_gdn);
    cudaGetSymbolAddress((void**)&fin,  g_fin);
    cudaGetSymbolAddress((void**)&al,   g_alpha);
    cudaGetSymbolAddress((void**)&be,   g_beta);

    dim3 gg(MTOT / 128, DIM / 128);
    sgemm_kernel<0><<<gg, 256>>>(x, Wq, bq, qlin);
    sgemm_kernel<0><<<gg, 256>>>(x, Wk, bk, klin);
    sgemm_kernel<0><<<gg, 256>>>(x, Wv, bv, vlin);
    sgemm_kernel<1><<<gg, 256>>>(x, Wg, bg, gate);
    ab_kernel<<<MTOT / 8, 256>>>(x, Wa, ba, Wb, bb, al, be);

    conv_silu_kernel<<<MTOT, 128>>>(qlin, cwq, cbq, qn, 1);
    conv_silu_kernel<<<MTOT, 128>>>(klin, cwk, cbk, kn, 1);
    conv_silu_kernel<<<MTOT, 128>>>(vlin, cwv, cbv, vn, 0);

    scan_kernel<<<256, 128>>>(qn, kn, vn, al, be, gdn);

    norm_gate_kernel<<<MTOT, 128>>>(gdn, norm_w, gate, fin);
    sgemm_kernel<0><<<gg, 256>>>(fin, Wo, bo, out);
}

// round 10
// speedup vs baseline: 1.1474x; 1.0983x over previous
#include <cuda_runtime.h>
#include <math.h>

#define BATCH 8
#define SLEN  2048
#define DIM   512
#define MTOT  (BATCH*SLEN)

// ---------------- scratch ----------------
__device__ float g_qlin[MTOT*DIM];
__device__ float g_klin[MTOT*DIM];
__device__ float g_vlin[MTOT*DIM];
__device__ float g_q[MTOT*DIM];
__device__ float g_k[MTOT*DIM];
__device__ float g_v[MTOT*DIM];
__device__ float g_gate[MTOT*DIM];
__device__ float g_gdn[MTOT*DIM];
__device__ float g_fin[MTOT*DIM];
__device__ float g_alpha[MTOT];
__device__ float g_beta[MTOT];

// ---------------- packed f32x2 helpers ----------------
__device__ __forceinline__ unsigned long long fma2_(unsigned long long a,
                                                    unsigned long long b,
                                                    unsigned long long c) {
    unsigned long long d;
    asm("fma.rn.f32x2 %0, %1, %2, %3;" : "=l"(d) : "l"(a), "l"(b), "l"(c));
    return d;
}
__device__ __forceinline__ unsigned long long mul2_(unsigned long long a,
                                                    unsigned long long b) {
    unsigned long long d;
    asm("mul.rn.f32x2 %0, %1, %2;" : "=l"(d) : "l"(a), "l"(b));
    return d;
}
__device__ __forceinline__ unsigned long long pk2_(float lo, float hi) {
    unsigned long long r;
    asm("mov.b64 %0, {%1, %2};" : "=l"(r)
        : "r"(__float_as_uint(lo)), "r"(__float_as_uint(hi)));
    return r;
}
__device__ __forceinline__ void up2_(unsigned long long a, float& lo, float& hi) {
    unsigned int l, h;
    asm("mov.b64 {%0, %1}, %2;" : "=r"(l), "=r"(h) : "l"(a));
    lo = __uint_as_float(l); hi = __uint_as_float(h);
}
__device__ __forceinline__ float hadd2_(unsigned long long a) {
    float lo, hi; up2_(a, lo, hi); return lo + hi;
}
__device__ __forceinline__ float wredsum_(float v) {
    #pragma unroll
    for (int off = 16; off; off >>= 1) v += __shfl_xor_sync(0xffffffffu, v, off);
    return v;
}
__device__ __forceinline__ float silu_(float x) { return x / (1.0f + __expf(-x)); }
__device__ __forceinline__ void cpasync16_(unsigned int dst, const void* src) {
    asm volatile("cp.async.cg.shared.global [%0], [%1], 16;"
                 :: "r"(dst), "l"(src) : "memory");
}

// ---------------- GEMM: C[M,512] = A @ W^T + bias, optional SiLU ----------------
template<int ACT>
__global__ void __launch_bounds__(256, 2) sgemm_kernel(
    const float* __restrict__ A, const float* __restrict__ W,
    const float* __restrict__ bias, float* __restrict__ C)
{
    __shared__ float As[2][16][140];
    __shared__ float Bs[2][16][140];
    const int tid = threadIdx.x;
    const int m0 = blockIdx.x * 128;
    const int n0 = blockIdx.y * 128;
    const int tx = tid & 15;
    const int ty = tid >> 4;
    const int lrow = tid >> 1;
    const int lcol = (tid & 1) * 8;

    const float* Aptr = A + (size_t)(m0 + lrow) * DIM + lcol;
    const float* Wptr = W + (size_t)(n0 + lrow) * DIM + lcol;

    float4 a0 = *(const float4*)(Aptr + 0);
    float4 a1 = *(const float4*)(Aptr + 4);
    float4 w0 = *(const float4*)(Wptr + 0);
    float4 w1 = *(const float4*)(Wptr + 4);

    unsigned long long acc[8][4];
    #pragma unroll
    for (int i = 0; i < 8; i++)
        #pragma unroll
        for (int j = 0; j < 4; j++) acc[i][j] = 0ULL;

    int buf = 0;
    #pragma unroll 1
    for (int kb = 0; kb < DIM / 16; ++kb) {
        As[buf][lcol+0][lrow] = a0.x; As[buf][lcol+1][lrow] = a0.y;
        As[buf][lcol+2][lrow] = a0.z; As[buf][lcol+3][lrow] = a0.w;
        As[buf][lcol+4][lrow] = a1.x; As[buf][lcol+5][lrow] = a1.y;
        As[buf][lcol+6][lrow] = a1.z; As[buf][lcol+7][lrow] = a1.w;
        Bs[buf][lcol+0][lrow] = w0.x; Bs[buf][lcol+1][lrow] = w0.y;
        Bs[buf][lcol+2][lrow] = w0.z; Bs[buf][lcol+3][lrow] = w0.w;
        Bs[buf][lcol+4][lrow] = w1.x; Bs[buf][lcol+5][lrow] = w1.y;
        Bs[buf][lcol+6][lrow] = w1.z; Bs[buf][lcol+7][lrow] = w1.w;
        __syncthreads();

        if (kb + 1 < DIM / 16) {
            int k0 = (kb + 1) * 16;
            a0 = *(const float4*)(Aptr + k0 + 0);
            a1 = *(const float4*)(Aptr + k0 + 4);
            w0 = *(const float4*)(Wptr + k0 + 0);
            w1 = *(const float4*)(Wptr + k0 + 4);
        }

        const float (*as)[140] = As[buf];
        const float (*bs)[140] = Bs[buf];
        #pragma unroll
        for (int kk = 0; kk < 16; ++kk) {
            float4 af0 = *(const float4*)&as[kk][ty * 8];
            float4 af1 = *(const float4*)&as[kk][ty * 8 + 4];
            float4 bf0 = *(const float4*)&bs[kk][tx * 8];
            float4 bf1 = *(const float4*)&bs[kk][tx * 8 + 4];
            unsigned long long bb[4] = {
                pk2_(bf0.x, bf0.y), pk2_(bf0.z, bf0.w),
                pk2_(bf1.x, bf1.y), pk2_(bf1.z, bf1.w)
            };
            float av[8] = {af0.x, af0.y, af0.z, af0.w, af1.x, af1.y, af1.z, af1.w};
            #pragma unroll
            for (int i = 0; i < 8; i++) {
                unsigned long long am = pk2_(av[i], av[i]);
                #pragma unroll
                for (int j = 0; j < 4; j++)
                    acc[i][j] = fma2_(am, bb[j], acc[i][j]);
            }
        }
        buf ^= 1;
    }

    float4 bs0 = *(const float4*)(bias + n0 + tx * 8);
    float4 bs1 = *(const float4*)(bias + n0 + tx * 8 + 4);
    #pragma unroll
    for (int i = 0; i < 8; i++) {
        float c[8];
        up2_(acc[i][0], c[0], c[1]);
        up2_(acc[i][1], c[2], c[3]);
        up2_(acc[i][2], c[4], c[5]);
        up2_(acc[i][3], c[6], c[7]);
        c[0] += bs0.x; c[1] += bs0.y; c[2] += bs0.z; c[3] += bs0.w;
        c[4] += bs1.x; c[5] += bs1.y; c[6] += bs1.z; c[7] += bs1.w;
        if (ACT == 1) {
            #pragma unroll
            for (int j = 0; j < 8; j++) c[j] = silu_(c[j]);
        }
        float* cp = C + (size_t)(m0 + ty * 8 + i) * DIM + n0 + tx * 8;
        *(float4*)(cp)     = make_float4(c[0], c[1], c[2], c[3]);
        *(float4*)(cp + 4) = make_float4(c[4], c[5], c[6], c[7]);
    }
}

// ---------------- alpha/beta GEMV + sigmoid ----------------
__global__ void __launch_bounds__(256) ab_kernel(
    const float* __restrict__ x,
    const float* __restrict__ Wa, const float* __restrict__ ba,
    const float* __restrict__ Wb, const float* __restrict__ bb,
    float* __restrict__ alpha, float* __restrict__ beta)
{
    const int warp = threadIdx.x >> 5, lane = threadIdx.x & 31;
    const int m = blockIdx.x * 8 + warp;
    const float* xr = x + (size_t)m * DIM;
    float sa = 0.f, sb = 0.f;
    #pragma unroll
    for (int i = 0; i < 4; i++) {
        float4 xv = *(const float4*)(xr + i * 128 + (lane << 2));
        float4 wa = *(const float4*)(Wa + i * 128 + (lane << 2));
        float4 wb = *(const float4*)(Wb + i * 128 + (lane << 2));
        sa += xv.x*wa.x + xv.y*wa.y + xv.z*wa.z + xv.w*wa.w;
        sb += xv.x*wb.x + xv.y*wb.y + xv.z*wb.z + xv.w*wb.w;
    }
    sa = wredsum_(sa);
    sb = wredsum_(sb);
    if (lane == 0) {
        alpha[m] = 1.0f / (1.0f + __expf(-(sa + ba[0])));
        beta[m]  = 1.0f / (1.0f + __expf(-(sb + bb[0])));
    }
}

// ---------------- depthwise causal conv(4) + SiLU (+ optional L2 norm) ----------------
__global__ void __launch_bounds__(128) conv_silu_kernel(
    const float* __restrict__ lin, const float* __restrict__ cw,
    const float* __restrict__ cb, float* __restrict__ outp, int do_l2)
{
    __shared__ float red[4];
    const int m = blockIdx.x;
    const int s = m & (SLEN - 1);
    const int c = threadIdx.x << 2;
    const int lane = threadIdx.x & 31;
    const int warp = threadIdx.x >> 5;

    float w[4][4];
    #pragma unroll
    for (int ch = 0; ch < 4; ++ch) {
        float4 wv = *(const float4*)(cw + (size_t)(c + ch) * 4);
        w[ch][0] = wv.x; w[ch][1] = wv.y; w[ch][2] = wv.z; w[ch][3] = wv.w;
    }
    float4 bv = *(const float4*)(cb + c);
    float y0 = bv.x, y1 = bv.y, y2 = bv.z, y3 = bv.w;
    #pragma unroll
    for (int tau = 0; tau < 4; ++tau) {
        int sp = s - 3 + tau;
        if (sp >= 0) {
            float4 xv = *(const float4*)(lin + (size_t)(m - 3 + tau) * DIM + c);
            y0 += w[0][tau] * xv.x;
            y1 += w[1][tau] * xv.y;
            y2 += w[2][tau] * xv.z;
            y3 += w[3][tau] * xv.w;
        }
    }
    y0 = silu_(y0); y1 = silu_(y1); y2 = silu_(y2); y3 = silu_(y3);
    float sc = 1.0f;
    if (do_l2) {
        float ss = wredsum_(y0*y0 + y1*y1 + y2*y2 + y3*y3);
        if (lane == 0) red[warp] = ss;
        __syncthreads();
        float tot = red[0] + red[1] + red[2] + red[3];
        sc = 1.0f / fmaxf(sqrtf(tot), 1e-12f);
    }
    *(float4*)(outp + (size_t)m * DIM + c) = make_float4(y0*sc, y1*sc, y2*sc, y3*sc);
}

// ---------------- gated delta-rule scan (2 steps fused per iteration) ---------
// 256 CTAs x 128 threads (4 warps, 4 rows/warp), 2 CTAs/SM.
// Per iteration (2 timesteps): ONE barrier, ONE wait, ONE reduction phase.
// Dots on Z_old: zk0_r, zq0_r, zk1_r, zq1_r (16) + c00=k0.q0, c01=k0.q1,
// ck=k0.k1, c11=k1.q1. Then w0, w1 sequentially; Z += w0*k0 + w1*k1.
__global__ void __launch_bounds__(128, 2) scan_kernel(
    const float* __restrict__ qn, const float* __restrict__ kn,
    const float* __restrict__ vn, const float* __restrict__ alpha,
    const float* __restrict__ beta, float* __restrict__ outp)
{
    const int warp = threadIdx.x >> 5;           // 0..3
    const int lane = threadIdx.x & 31;
    const int cta  = blockIdx.x;                 // 0..255
    const int b    = cta >> 5;
    const int i0   = ((cta & 31) << 4) + (warp << 2);

    const float* kp = kn + (size_t)b * SLEN * DIM;
    const float* qp = qn + (size_t)b * SLEN * DIM;
    const float* vp = vn + (size_t)b * SLEN * DIM + i0;
    const float* ap = alpha + (size_t)b * SLEN;
    const float* bp = beta  + (size_t)b * SLEN;
    float* op = outp + (size_t)b * SLEN * DIM + i0;

    // smem: 3 buffers x [k0|q0|k1|q1] x 512 floats = 24 KB
    __shared__ __align__(16) float sbuf[3][2048];
    unsigned int sbase = (unsigned int)__cvta_generic_to_shared(sbuf);
    // staging: warp w copies section w (k0,q0,k1,q1); lane does 4 float4s
    const float* gsec = ((warp & 1) ? qp : kp) + (warp >> 1) * DIM;
    const unsigned int soff = warp * 2048 + lane * 16;   // bytes within buffer

    // prologue: iter0 -> buf0, iter1 -> buf1
    #pragma unroll
    for (int m = 0; m < 4; m++)
        cpasync16_(sbase + soff + m * 512, gsec + (lane + 32 * m) * 4);
    asm volatile("cp.async.commit_group;" ::: "memory");
    #pragma unroll
    for (int m = 0; m < 4; m++)
        cpasync16_(sbase + 8192 + soff + m * 512, gsec + 2 * DIM + (lane + 32 * m) * 4);
    asm volatile("cp.async.commit_group;" ::: "memory");

    unsigned long long z[4][8];
    #pragma unroll
    for (int r = 0; r < 4; r++)
        #pragma unroll
        for (int e = 0; e < 8; e++) z[r][e] = 0ULL;

    float A = 1.0f;
    const unsigned FULL = 0xffffffffu;
    int cur = 0, nxt = 2;

    // output-lane mapping: lanes with (lane&3)==2 store.
    // step = (lane&4)?1:0 ; row = bit4 + 2*bit3
    const bool isout = (lane & 3) == 2;
    const int ostep = (lane >> 2) & 1;
    const int orow = ((lane >> 4) & 1) + (((lane >> 3) & 1) << 1);

    #pragma unroll 1
    for (int i = 0; i < SLEN / 2; ++i) {
        asm volatile("cp.async.wait_group 1;" ::: "memory");
        __syncthreads();
        if (i + 2 < SLEN / 2) {
            const float* gs2 = gsec + (size_t)(2 * i + 4) * DIM;
            #pragma unroll
            for (int m = 0; m < 4; m++)
                cpasync16_(sbase + nxt * 8192 + soff + m * 512, gs2 + (lane + 32 * m) * 4);
        }
        asm volatile("cp.async.commit_group;" ::: "memory");

        // read k0,q0,k1,q1 from smem
        unsigned long long kc0[8], qc0[8], kc1[8], qc1[8];
        {
            const float4* f0 = (const float4*)&sbuf[cur][0];
            const float4* f1 = (const float4*)&sbuf[cur][512];
            const float4* f2 = (const float4*)&sbuf[cur][1024];
            const float4* f3 = (const float4*)&sbuf[cur][1536];
            #pragma unroll
            for (int m = 0; m < 4; m++) {
                float4 u;
                u = f0[m * 32 + lane]; kc0[2*m] = pk2_(u.x,u.y); kc0[2*m+1] = pk2_(u.z,u.w);
                u = f1[m * 32 + lane]; qc0[2*m] = pk2_(u.x,u.y); qc0[2*m+1] = pk2_(u.z,u.w);
                u = f2[m * 32 + lane]; kc1[2*m] = pk2_(u.x,u.y); kc1[2*m+1] = pk2_(u.z,u.w);
                u = f3[m * 32 + lane]; qc1[2*m] = pk2_(u.x,u.y); qc1[2*m+1] = pk2_(u.z,u.w);
            }
        }
        float4 v0 = *(const float4*)(vp + (size_t)(2 * i) * DIM);
        float4 v1 = *(const float4*)(vp + (size_t)(2 * i + 1) * DIM);
        float2 a2 = *(const float2*)(ap + 2 * i);
        float2 b2 = *(const float2*)(bp + 2 * i);

        // 20 simultaneous dots on Z_old
        unsigned long long zka[4] = {0,0,0,0}, zqa[4] = {0,0,0,0};
        unsigned long long zkb[4] = {0,0,0,0}, zqb[4] = {0,0,0,0};
        unsigned long long c00a = 0, c01a = 0, cka = 0, c11a = 0;
        #pragma unroll
        for (int e = 0; e < 8; e++) {
            #pragma unroll
            for (int r = 0; r < 4; r++) {
                zka[r] = fma2_(z[r][e], kc0[e], zka[r]);
                zqa[r] = fma2_(z[r][e], qc0[e], zqa[r]);
                zkb[r] = fma2_(z[r][e], kc1[e], zkb[r]);
                zqb[r] = fma2_(z[r][e], qc1[e], zqb[r]);
            }
            c00a = fma2_(kc0[e], qc0[e], c00a);
            c01a = fma2_(kc0[e], qc1[e], c01a);
            cka  = fma2_(kc0[e], kc1[e], cka);
            c11a = fma2_(kc1[e], qc1[e], c11a);
        }
        // 16-value packed butterfly; value idx bits: b0=lane4,b1=lane3,b2=lane2,b3=lane1
        // order: [zk0_0..3, zk1_0..3, zq0_0..3, zq1_0..3]
        float d[16];
        d[0]=hadd2_(zka[0]); d[1]=hadd2_(zka[1]); d[2]=hadd2_(zka[2]); d[3]=hadd2_(zka[3]);
        d[4]=hadd2_(zkb[0]); d[5]=hadd2_(zkb[1]); d[6]=hadd2_(zkb[2]); d[7]=hadd2_(zkb[3]);
        d[8]=hadd2_(zqa[0]); d[9]=hadd2_(zqa[1]); d[10]=hadd2_(zqa[2]); d[11]=hadd2_(zqa[3]);
        d[12]=hadd2_(zqb[0]); d[13]=hadd2_(zqb[1]); d[14]=hadd2_(zqb[2]); d[15]=hadd2_(zqb[3]);
        float f;
        {
            float x[16];
            #pragma unroll
            for (int j = 0; j < 16; j++) x[j] = d[j] + __shfl_xor_sync(FULL, d[j], 16);
            bool s4 = (lane & 16) != 0;
            float w8[8];
            #pragma unroll
            for (int j = 0; j < 8; j++) w8[j] = s4 ? x[2*j+1] : x[2*j];
            float y8[8];
            #pragma unroll
            for (int j = 0; j < 8; j++) y8[j] = w8[j] + __shfl_xor_sync(FULL, w8[j], 8);
            bool s3 = (lane & 8) != 0;
            float u4[4];
            #pragma unroll
            for (int j = 0; j < 4; j++) u4[j] = s3 ? y8[2*j+1] : y8[2*j];
            float t4[4];
            #pragma unroll
            for (int j = 0; j < 4; j++) t4[j] = u4[j] + __shfl_xor_sync(FULL, u4[j], 4);
            bool s2 = (lane & 4) != 0;
            float sv[2];
            sv[0] = s2 ? t4[1] : t4[0];
            sv[1] = s2 ? t4[3] : t4[2];
            float rv[2];
            rv[0] = sv[0] + __shfl_xor_sync(FULL, sv[0], 2);
            rv[1] = sv[1] + __shfl_xor_sync(FULL, sv[1], 2);
            float qv = (lane & 2) ? rv[1] : rv[0];
            f = qv + __shfl_xor_sync(FULL, qv, 1);
        }
        // 4 scalar crosses packed: order [c00, c01, ck, c11]
        float c00, c01, ck, c11;
        {
            float e0 = hadd2_(c00a), e1 = hadd2_(c01a), e2 = hadd2_(cka), e3 = hadd2_(c11a);
            float x0 = e0 + __shfl_xor_sync(FULL, e0, 16);
            float x1 = e1 + __shfl_xor_sync(FULL, e1, 16);
            float x2 = e2 + __shfl_xor_sync(FULL, e2, 16);
            float x3 = e3 + __shfl_xor_sync(FULL, e3, 16);
            bool s4 = (lane & 16) != 0;
            float g0 = s4 ? x1 : x0;
            float g1 = s4 ? x3 : x2;
            float y0 = g0 + __shfl_xor_sync(FULL, g0, 8);
            float y1 = g1 + __shfl_xor_sync(FULL, g1, 8);
            float h = (lane & 8) ? y1 : y0;
            h += __shfl_xor_sync(FULL, h, 4);
            h += __shfl_xor_sync(FULL, h, 2);
            h += __shfl_xor_sync(FULL, h, 1);
            c00 = __shfl_sync(FULL, h, 0);
            c01 = __shfl_sync(FULL, h, 16);
            ck  = __shfl_sync(FULL, h, 8);
            c11 = __shfl_sync(FULL, h, 24);
        }
        // broadcast zk values
        float zk0r[4], zk1r[4];
        zk0r[0] = __shfl_sync(FULL, f, 0);
        zk0r[1] = __shfl_sync(FULL, f, 16);
        zk0r[2] = __shfl_sync(FULL, f, 8);
        zk0r[3] = __shfl_sync(FULL, f, 24);
        zk1r[0] = __shfl_sync(FULL, f, 4);
        zk1r[1] = __shfl_sync(FULL, f, 20);
        zk1r[2] = __shfl_sync(FULL, f, 12);
        zk1r[3] = __shfl_sync(FULL, f, 28);

        // scalar algebra
        float A1 = A * a2.x;
        float rA1 = 1.0f / A1;
        float ab0 = a2.x * b2.x;
        float vv0[4] = {v0.x, v0.y, v0.z, v0.w};
        float vv1[4] = {v1.x, v1.y, v1.z, v1.w};
        float w0v[4], w1v[4];
        #pragma unroll
        for (int r = 0; r < 4; r++)
            w0v[r] = (b2.x * vv0[r] - ab0 * (A * zk0r[r])) * rA1;
        float A2f = A1 * a2.y;
        float rA2 = 1.0f / A2f;
        float ab1 = a2.y * b2.y;
        #pragma unroll
        for (int r = 0; r < 4; r++) {
            float sk1 = A1 * (zk1r[r] + w0v[r] * ck);
            w1v[r] = (b2.y * vv1[r] - ab1 * sk1) * rA2;
        }

        // fused state update: Z += w0*k0 + w1*k1
        #pragma unroll
        for (int r = 0; r < 4; r++) {
            unsigned long long W0 = pk2_(w0v[r], w0v[r]);
            unsigned long long W1 = pk2_(w1v[r], w1v[r]);
            #pragma unroll
            for (int e = 0; e < 8; e++)
                z[r][e] = fma2_(W1, kc1[e], fma2_(W0, kc0[e], z[r][e]));
        }

        // outputs
        if (isout) {
            float o;
            if (ostep == 0) o = A1 * (f + w0v[orow] * c00);
            else            o = A2f * (f + w0v[orow] * c01 + w1v[orow] * c11);
            op[(size_t)(2 * i + ostep) * DIM + orow] = o;
        }

        A = A2f;
        if ((i & 7) == 7) {
            unsigned long long AA = pk2_(A, A);
            #pragma unroll
            for (int r = 0; r < 4; r++)
                #pragma unroll
                for (int e = 0; e < 8; e++) z[r][e] = mul2_(z[r][e], AA);
            A = 1.0f;
        }

        cur = (cur == 2) ? 0 : cur + 1;
        nxt = (nxt == 2) ? 0 : nxt + 1;
    }
}

// ---------------- zero-centered RMSNorm * gate ----------------
__global__ void __launch_bounds__(128) norm_gate_kernel(
    const float* __restrict__ gdn, const float* __restrict__ norm_w,
    const float* __restrict__ gate, float* __restrict__ fin)
{
    __shared__ float rs[4], rq[4];
    const int m = blockIdx.x;
    const int c = threadIdx.x << 2;
    const int lane = threadIdx.x & 31;
    const int warp = threadIdx.x >> 5;

    float4 xv = *(const float4*)(gdn + (size_t)m * DIM + c);
    float s = wredsum_(xv.x + xv.y + xv.z + xv.w);
    float q = wredsum_(xv.x*xv.x + xv.y*xv.y + xv.z*xv.z + xv.w*xv.w);
    if (lane == 0) { rs[warp] = s; rq[warp] = q; }
    __syncthreads();
    float sum = rs[0] + rs[1] + rs[2] + rs[3];
    float sq  = rq[0] + rq[1] + rq[2] + rq[3];
    float mean = sum * (1.0f / DIM);
    float var  = sq * (1.0f / DIM) - mean * mean;
    float inv  = rsqrtf(var + 1e-5f);

    float4 wv = *(const float4*)(norm_w + c);
    float4 gv = *(const float4*)(gate + (size_t)m * DIM + c);
    float4 r;
    r.x = (xv.x - mean) * inv * wv.x * gv.x;
    r.y = (xv.y - mean) * inv * wv.y * gv.y;
    r.z = (xv.z - mean) * inv * wv.z * gv.z;
    r.w = (xv.w - mean) * inv * wv.w * gv.w;
    *(float4*)(fin + (size_t)m * DIM + c) = r;
}

// ---------------- launch ----------------
extern "C" void kernel_launch(void* const* d_in, const int* in_sizes, int n_in,
                              void* d_out, int out_size) {
    const float* x    = (const float*)d_in[0];
    const float* Wq   = (const float*)d_in[1];
    const float* bq   = (const float*)d_in[2];
    const float* Wk   = (const float*)d_in[3];
    const float* bk   = (const float*)d_in[4];
    const float* Wv   = (const float*)d_in[5];
    const float* bv   = (const float*)d_in[6];
    const float* Wa   = (const float*)d_in[7];
    const float* ba   = (const float*)d_in[8];
    const float* Wb   = (const float*)d_in[9];
    const float* bb   = (const float*)d_in[10];
    const float* cwq  = (const float*)d_in[11];
    const float* cbq  = (const float*)d_in[12];
    const float* cwk  = (const float*)d_in[13];
    const float* cbk  = (const float*)d_in[14];
    const float* cwv  = (const float*)d_in[15];
    const float* cbv  = (const float*)d_in[16];
    const float* norm_w = (const float*)d_in[17];
    const float* Wg   = (const float*)d_in[18];
    const float* bg   = (const float*)d_in[19];
    const float* Wo   = (const float*)d_in[20];
    const float* bo   = (const float*)d_in[21];
    float* out = (float*)d_out;

    float *qlin, *klin, *vlin, *qn, *kn, *vn, *gate, *gdn, *fin, *al, *be;
    cudaGetSymbolAddress((void**)&qlin, g_qlin);
    cudaGetSymbolAddress((void**)&klin, g_klin);
    cudaGetSymbolAddress((void**)&vlin, g_vlin);
    cudaGetSymbolAddress((void**)&qn,   g_q);
    cudaGetSymbolAddress((void**)&kn,   g_k);
    cudaGetSymbolAddress((void**)&vn,   g_v);
    cudaGetSymbolAddress((void**)&gate, g_gate);
    cudaGetSymbolAddress((void**)&gdn,  g_gdn);
    cudaGetSymbolAddress((void**)&fin,  g_fin);
    cudaGetSymbolAddress((void**)&al,   g_alpha);
    cudaGetSymbolAddress((void**)&be,   g_beta);

    dim3 gg(MTOT / 128, DIM / 128);
    sgemm_kernel<0><<<gg, 256>>>(x, Wq, bq, qlin);
    sgemm_kernel<0><<<gg, 256>>>(x, Wk, bk, klin);
    sgemm_kernel<0><<<gg, 256>>>(x, Wv, bv, vlin);
    sgemm_kernel<1><<<gg, 256>>>(x, Wg, bg, gate);
    ab_kernel<<<MTOT / 8, 256>>>(x, Wa, ba, Wb, bb, al, be);

    conv_silu_kernel<<<MTOT, 128>>>(qlin, cwq, cbq, qn, 1);
    conv_silu_kernel<<<MTOT, 128>>>(klin, cwk, cbk, kn, 1);
    conv_silu_kernel<<<MTOT, 128>>>(vlin, cwv, cbv, vn, 0);

    scan_kernel<<<256, 128>>>(qn, kn, vn, al, be, gdn);

    norm_gate_kernel<<<MTOT, 128>>>(gdn, norm_w, gate, fin);
    sgemm_kernel<0><<<gg, 256>>>(fin, Wo, bo, out);
}